// round 2
// baseline (speedup 1.0000x reference)
#include <cuda_runtime.h>
#include <cuda_bf16.h>
#include <cstdint>

// Problem constants (match reference)
#define NMAX      50000
#define IN_DIM    256
#define H_DIM     128
#define OUT_DIM   64
#define K_STEPS   10
#define ALPHA_F   0.1f

// -------- scratch (no allocation allowed -> device globals) --------
__device__ float gX1[(size_t)NMAX * H_DIM];    // features @ W1
__device__ float gP1[(size_t)NMAX * H_DIM];    // prop(X1)
__device__ float gX2[(size_t)NMAX * OUT_DIM];  // (P1+b1) @ W2
__device__ float gH [(size_t)NMAX * OUT_DIM];  // h = prop(X2)+b2
__device__ float gA [(size_t)NMAX * OUT_DIM];  // ping
__device__ float gB [(size_t)NMAX * OUT_DIM];  // pong
__device__ int   gIdxIs64;                     // 1 if edge_index stored as int64

// ------------- dtype detection: int64 vs int32 edge_index -------------
// If data is int64, the first 64 values are all in [0, N). If int32, the
// int64 reinterpretation packs two random indices -> value >= 2^32 almost surely.
__global__ void detect_idx_dtype(const void* __restrict__ ei, int N)
{
    const long long* p = (const long long*)ei;
    int ok = 1;
    for (int i = 0; i < 64; i++) {
        long long v = p[i];
        if (v < 0 || v >= N) { ok = 0; break; }
    }
    gIdxIs64 = ok;
}

// ---------------- SGEMM: C[M,N] = (A + a_bias) @ B ----------------
template<int BM, int BN, int BK, int TM, int TN>
__global__ void sgemm_bias(int M, int N, int K,
                           const float* __restrict__ A,
                           const float* __restrict__ B,
                           float* __restrict__ C,
                           const float* __restrict__ a_bias)
{
    constexpr int THREADS = (BM / TM) * (BN / TN);
    __shared__ float As[BK][BM];
    __shared__ float Bs[BK][BN];

    const int tid = threadIdx.x;
    const int tc  = tid % (BN / TN);
    const int tr  = tid / (BN / TN);
    const int rowBase = blockIdx.x * BM;
    const int colBase = blockIdx.y * BN;

    float acc[TM][TN];
#pragma unroll
    for (int i = 0; i < TM; i++)
#pragma unroll
        for (int j = 0; j < TN; j++) acc[i][j] = 0.0f;

    constexpr int A_VECS = BM * BK / (THREADS * 4);
    constexpr int B_VECS = BK * BN / (THREADS * 4);

    for (int k0 = 0; k0 < K; k0 += BK) {
#pragma unroll
        for (int i = 0; i < A_VECS; i++) {
            int lin = (tid + i * THREADS) * 4;
            int r = lin / BK, c = lin % BK;
            int grow = rowBase + r;
            float4 v = make_float4(0.f, 0.f, 0.f, 0.f);
            if (grow < M)
                v = *reinterpret_cast<const float4*>(A + (size_t)grow * K + k0 + c);
            if (a_bias) {
                v.x += a_bias[k0 + c + 0];
                v.y += a_bias[k0 + c + 1];
                v.z += a_bias[k0 + c + 2];
                v.w += a_bias[k0 + c + 3];
            }
            As[c + 0][r] = v.x;
            As[c + 1][r] = v.y;
            As[c + 2][r] = v.z;
            As[c + 3][r] = v.w;
        }
#pragma unroll
        for (int i = 0; i < B_VECS; i++) {
            int lin = (tid + i * THREADS) * 4;
            int r = lin / BN, c = lin % BN;
            *reinterpret_cast<float4*>(&Bs[r][c]) =
                *reinterpret_cast<const float4*>(B + (size_t)(k0 + r) * N + colBase + c);
        }
        __syncthreads();

#pragma unroll
        for (int k = 0; k < BK; k++) {
            float ra[TM], rb[TN];
#pragma unroll
            for (int i = 0; i < TM; i++) ra[i] = As[k][tr * TM + i];
#pragma unroll
            for (int j = 0; j < TN; j++) rb[j] = Bs[k][tc * TN + j];
#pragma unroll
            for (int i = 0; i < TM; i++)
#pragma unroll
                for (int j = 0; j < TN; j++) acc[i][j] += ra[i] * rb[j];
        }
        __syncthreads();
    }

#pragma unroll
    for (int i = 0; i < TM; i++) {
        int grow = rowBase + tr * TM + i;
        if (grow >= M) continue;
#pragma unroll
        for (int j = 0; j < TN; j += 4) {
            float4 v = make_float4(acc[i][j], acc[i][j + 1], acc[i][j + 2], acc[i][j + 3]);
            *reinterpret_cast<float4*>(C + (size_t)grow * N + colBase + tc * TN + j) = v;
        }
    }
}

// ------------- edge-weighted scatter: out[dst] += wscale*w*x[src] -------------
// One thread per (edge, float4-chunk). sm_90+ vector red.global.add.v4.f32.
template<int DIM>
__global__ void scatter_prop(const void* __restrict__ ei,
                             const float* __restrict__ ew,
                             const float* __restrict__ x,
                             float* __restrict__ out,
                             int E, float wscale)
{
    constexpr int CH = DIM / 4;          // float4 chunks per edge
    constexpr int SH = (CH == 16) ? 4 : 5;
    int idx = blockIdx.x * blockDim.x + threadIdx.x;
    if (idx >= E * CH) return;
    int e = idx >> SH;
    int c = idx & (CH - 1);

    long long s, d;
    if (gIdxIs64) {
        const long long* p = (const long long*)ei;
        s = __ldg(&p[e]);
        d = __ldg(&p[E + e]);
    } else {
        const int* p = (const int*)ei;
        s = __ldg(&p[e]);
        d = __ldg(&p[E + e]);
    }
    float w = __ldg(&ew[e]) * wscale;

    float4 v = __ldg(reinterpret_cast<const float4*>(x + s * DIM) + c);
    float4 r;
    r.x = w * v.x; r.y = w * v.y; r.z = w * v.z; r.w = w * v.w;

    float* p = out + d * DIM + (c << 2);
    asm volatile("red.global.add.v4.f32 [%0], {%1, %2, %3, %4};"
                 :: "l"(p), "f"(r.x), "f"(r.y), "f"(r.z), "f"(r.w)
                 : "memory");
}

// out4[i] = ALPHA * h4[i]
__global__ void init_alpha(float4* __restrict__ out, const float4* __restrict__ h, int n4)
{
    int i = blockIdx.x * blockDim.x + threadIdx.x;
    if (i >= n4) return;
    float4 v = h[i];
    v.x *= ALPHA_F; v.y *= ALPHA_F; v.z *= ALPHA_F; v.w *= ALPHA_F;
    out[i] = v;
}

// x[i, :] += b2 (DIM=64, float4 view: 16 vecs per row)
__global__ void add_bias64(float4* __restrict__ x, int n4, const float* __restrict__ b)
{
    int i = blockIdx.x * blockDim.x + threadIdx.x;
    if (i >= n4) return;
    float4 bv = reinterpret_cast<const float4*>(b)[i & 15];
    float4 v = x[i];
    v.x += bv.x; v.y += bv.y; v.z += bv.z; v.w += bv.w;
    x[i] = v;
}

__global__ void fill_tail(float* __restrict__ out, int start, int total)
{
    int i = start + blockIdx.x * blockDim.x + threadIdx.x;
    if (i < total) out[i] = 10.0f;
}

extern "C" void kernel_launch(void* const* d_in, const int* in_sizes, int n_in,
                              void* d_out, int out_size)
{
    const float* features = (const float*)d_in[0];
    const void*  ei       = d_in[1];
    const float* ew       = (const float*)d_in[2];
    const float* W1       = (const float*)d_in[3];
    const float* b1       = (const float*)d_in[4];
    const float* W2       = (const float*)d_in[5];
    const float* b2       = (const float*)d_in[6];
    float*       out      = (float*)d_out;

    const int N = in_sizes[0] / IN_DIM;
    const int E = in_sizes[2];

    float *X1, *P1, *X2, *H, *A, *B;
    cudaGetSymbolAddress((void**)&X1, gX1);
    cudaGetSymbolAddress((void**)&P1, gP1);
    cudaGetSymbolAddress((void**)&X2, gX2);
    cudaGetSymbolAddress((void**)&H,  gH);
    cudaGetSymbolAddress((void**)&A,  gA);
    cudaGetSymbolAddress((void**)&B,  gB);

    detect_idx_dtype<<<1, 1>>>(ei, N);

    // ---- layer 1: X1 = features @ W1 ----
    {
        dim3 grid((N + 127) / 128, H_DIM / 128);
        sgemm_bias<128, 128, 16, 8, 8><<<grid, 256>>>(N, H_DIM, IN_DIM, features, W1, X1, nullptr);
    }
    // P1 = prop(X1)
    cudaMemsetAsync(P1, 0, (size_t)N * H_DIM * sizeof(float));
    {
        int total = E * (H_DIM / 4);
        scatter_prop<H_DIM><<<(total + 255) / 256, 256>>>(ei, ew, X1, P1, E, 1.0f);
    }
    // ---- layer 2: X2 = (P1 + b1) @ W2 ----
    {
        dim3 grid((N + 127) / 128, OUT_DIM / 64);
        sgemm_bias<128, 64, 16, 8, 4><<<grid, 256>>>(N, OUT_DIM, H_DIM, P1, W2, X2, b1);
    }
    // H = prop(X2) + b2
    cudaMemsetAsync(H, 0, (size_t)N * OUT_DIM * sizeof(float));
    {
        int total = E * (OUT_DIM / 4);
        scatter_prop<OUT_DIM><<<(total + 255) / 256, 256>>>(ei, ew, X2, H, E, 1.0f);
    }
    {
        int n4 = N * (OUT_DIM / 4);
        add_bias64<<<(n4 + 255) / 256, 256>>>((float4*)H, n4, b2);
    }

    // ---- APPNP: x_{k+1} = (1-a)*prop(x_k) + a*h ----
    // fused: target := a*h, then scatter with weight scale (1-a)
    const float* xcur = H;
    const int n4 = N * (OUT_DIM / 4);
    const int stot = E * (OUT_DIM / 4);
    for (int k = 0; k < K_STEPS; k++) {
        float* xnext = (k == K_STEPS - 1) ? out : ((k & 1) ? B : A);
        init_alpha<<<(n4 + 255) / 256, 256>>>((float4*)xnext, (const float4*)H, n4);
        scatter_prop<OUT_DIM><<<(stot + 255) / 256, 256>>>(ei, ew, xcur, xnext, E, 1.0f - ALPHA_F);
        xcur = xnext;
    }

    // tail (reference returns (x, 10); fill any extra outputs with 10)
    int tail = out_size - N * OUT_DIM;
    if (tail > 0)
        fill_tail<<<(tail + 255) / 256, 256>>>(out, N * OUT_DIM, out_size);
}

// round 3
// speedup vs baseline: 1.5036x; 1.5036x over previous
#include <cuda_runtime.h>
#include <cuda_bf16.h>
#include <cstdint>

// Problem constants (match reference)
#define NMAX      50000
#define EMAX      800000
#define IN_DIM    256
#define H_DIM     128
#define OUT_DIM   64
#define K_STEPS   10
#define ALPHA_F   0.1f

// -------- scratch (no allocation allowed -> device globals) --------
__device__ float gX1[(size_t)NMAX * H_DIM];    // features @ W1
__device__ float gP1[(size_t)NMAX * H_DIM];    // prop(X1)
__device__ float gX2[(size_t)NMAX * OUT_DIM];  // (P1+b1) @ W2
__device__ float gH [(size_t)NMAX * OUT_DIM];  // h = prop(X2)+b2
__device__ float gA [(size_t)NMAX * OUT_DIM];  // ping
__device__ float gB [(size_t)NMAX * OUT_DIM];  // pong
__device__ int   gIdxIs64;                     // 1 if edge_index stored as int64
// CSR scratch
__device__ int   gCount[NMAX];
__device__ int   gRowPtr[NMAX + 1];
__device__ int   gWp[NMAX];
__device__ int2  gCsr[EMAX];                   // (src, w-bits) sorted by dst

// ------------- dtype detection: int64 vs int32 edge_index -------------
__global__ void detect_idx_dtype(const void* __restrict__ ei, int N)
{
    const long long* p = (const long long*)ei;
    int ok = 1;
    for (int i = 0; i < 64; i++) {
        long long v = p[i];
        if (v < 0 || v >= N) { ok = 0; break; }
    }
    gIdxIs64 = ok;
}

// ------------- CSR build -------------
__global__ void hist_dst(const void* __restrict__ ei, int E)
{
    int e = blockIdx.x * blockDim.x + threadIdx.x;
    if (e >= E) return;
    int d;
    if (gIdxIs64) d = (int)((const long long*)ei)[E + e];
    else          d = ((const int*)ei)[E + e];
    atomicAdd(&gCount[d], 1);
}

// single-block exclusive scan over gCount -> gRowPtr / gWp
__global__ void scan_rowptr(int N, int E)
{
    __shared__ int sSum[1024];
    const int tid = threadIdx.x;
    const int chunk = (N + 1023) / 1024;
    const int lo = tid * chunk;
    const int hi = min(lo + chunk, N);

    int s = 0;
    for (int i = lo; i < hi; i++) s += gCount[i];
    sSum[tid] = s;
    __syncthreads();

    // Hillis-Steele inclusive scan on 1024 partials
    for (int off = 1; off < 1024; off <<= 1) {
        int v = (tid >= off) ? sSum[tid - off] : 0;
        __syncthreads();
        sSum[tid] += v;
        __syncthreads();
    }
    int run = (tid == 0) ? 0 : sSum[tid - 1];   // exclusive offset for this chunk
    for (int i = lo; i < hi; i++) {
        gRowPtr[i] = run;
        gWp[i]     = run;
        run += gCount[i];
    }
    if (tid == 1023) gRowPtr[N] = E;
}

__global__ void fill_csr(const void* __restrict__ ei, const float* __restrict__ ew, int E)
{
    int e = blockIdx.x * blockDim.x + threadIdx.x;
    if (e >= E) return;
    int s, d;
    if (gIdxIs64) {
        const long long* p = (const long long*)ei;
        s = (int)p[e];
        d = (int)p[E + e];
    } else {
        const int* p = (const int*)ei;
        s = p[e];
        d = p[E + e];
    }
    int pos = atomicAdd(&gWp[d], 1);
    gCsr[pos] = make_int2(s, __float_as_int(ew[e]));
}

// ---------------- SGEMM: C[M,N] = (A + a_bias) @ B ----------------
template<int BM, int BN, int BK, int TM, int TN>
__global__ void sgemm_bias(int M, int N, int K,
                           const float* __restrict__ A,
                           const float* __restrict__ B,
                           float* __restrict__ C,
                           const float* __restrict__ a_bias)
{
    constexpr int THREADS = (BM / TM) * (BN / TN);
    __shared__ float As[BK][BM];
    __shared__ float Bs[BK][BN];

    const int tid = threadIdx.x;
    const int tc  = tid % (BN / TN);
    const int tr  = tid / (BN / TN);
    const int rowBase = blockIdx.x * BM;
    const int colBase = blockIdx.y * BN;

    float acc[TM][TN];
#pragma unroll
    for (int i = 0; i < TM; i++)
#pragma unroll
        for (int j = 0; j < TN; j++) acc[i][j] = 0.0f;

    constexpr int A_VECS = BM * BK / (THREADS * 4);
    constexpr int B_VECS = BK * BN / (THREADS * 4);

    for (int k0 = 0; k0 < K; k0 += BK) {
#pragma unroll
        for (int i = 0; i < A_VECS; i++) {
            int lin = (tid + i * THREADS) * 4;
            int r = lin / BK, c = lin % BK;
            int grow = rowBase + r;
            float4 v = make_float4(0.f, 0.f, 0.f, 0.f);
            if (grow < M)
                v = *reinterpret_cast<const float4*>(A + (size_t)grow * K + k0 + c);
            if (a_bias) {
                v.x += a_bias[k0 + c + 0];
                v.y += a_bias[k0 + c + 1];
                v.z += a_bias[k0 + c + 2];
                v.w += a_bias[k0 + c + 3];
            }
            As[c + 0][r] = v.x;
            As[c + 1][r] = v.y;
            As[c + 2][r] = v.z;
            As[c + 3][r] = v.w;
        }
#pragma unroll
        for (int i = 0; i < B_VECS; i++) {
            int lin = (tid + i * THREADS) * 4;
            int r = lin / BN, c = lin % BN;
            *reinterpret_cast<float4*>(&Bs[r][c]) =
                *reinterpret_cast<const float4*>(B + (size_t)(k0 + r) * N + colBase + c);
        }
        __syncthreads();

#pragma unroll
        for (int k = 0; k < BK; k++) {
            float ra[TM], rb[TN];
#pragma unroll
            for (int i = 0; i < TM; i++) ra[i] = As[k][tr * TM + i];
#pragma unroll
            for (int j = 0; j < TN; j++) rb[j] = Bs[k][tc * TN + j];
#pragma unroll
            for (int i = 0; i < TM; i++)
#pragma unroll
                for (int j = 0; j < TN; j++) acc[i][j] += ra[i] * rb[j];
        }
        __syncthreads();
    }

#pragma unroll
    for (int i = 0; i < TM; i++) {
        int grow = rowBase + tr * TM + i;
        if (grow >= M) continue;
#pragma unroll
        for (int j = 0; j < TN; j += 4) {
            float4 v = make_float4(acc[i][j], acc[i][j + 1], acc[i][j + 2], acc[i][j + 3]);
            *reinterpret_cast<float4*>(C + (size_t)grow * N + colBase + tc * TN + j) = v;
        }
    }
}

// ------------- CSR gather prop -------------
// out[n,:] = wscale * sum_{e in in(n)} w_e * x[src_e,:]  (+ ascale*addv[n,:]) (+ bias[:])
// One warp per node; lane l owns columns {l, l+32, ...}.
template<int DIM>
__global__ void gather_prop(const float* __restrict__ x,
                            float* __restrict__ out,
                            const float* __restrict__ addv,  // may be null
                            const float* __restrict__ bias,  // may be null
                            int N, float wscale, float ascale)
{
    constexpr int R = DIM / 32;
    int warp = (blockIdx.x * blockDim.x + threadIdx.x) >> 5;
    int lane = threadIdx.x & 31;
    if (warp >= N) return;

    int e   = gRowPtr[warp];
    int end = gRowPtr[warp + 1];

    float acc[R];
#pragma unroll
    for (int j = 0; j < R; j++) acc[j] = 0.0f;

    // unroll-by-2 over edges for MLP
    for (; e + 1 < end; e += 2) {
        int2 sw0 = __ldg(&gCsr[e]);
        int2 sw1 = __ldg(&gCsr[e + 1]);
        float w0 = __int_as_float(sw0.y);
        float w1 = __int_as_float(sw1.y);
        const float* r0 = x + (size_t)sw0.x * DIM + lane;
        const float* r1 = x + (size_t)sw1.x * DIM + lane;
#pragma unroll
        for (int j = 0; j < R; j++) {
            float v0 = __ldg(r0 + 32 * j);
            float v1 = __ldg(r1 + 32 * j);
            acc[j] += w0 * v0;
            acc[j] += w1 * v1;
        }
    }
    if (e < end) {
        int2 sw = __ldg(&gCsr[e]);
        float w = __int_as_float(sw.y);
        const float* r = x + (size_t)sw.x * DIM + lane;
#pragma unroll
        for (int j = 0; j < R; j++) acc[j] += w * __ldg(r + 32 * j);
    }

    float* o = out + (size_t)warp * DIM + lane;
#pragma unroll
    for (int j = 0; j < R; j++) {
        float v = wscale * acc[j];
        if (addv) v += ascale * addv[(size_t)warp * DIM + lane + 32 * j];
        if (bias) v += bias[lane + 32 * j];
        o[32 * j] = v;
    }
}

__global__ void fill_tail(float* __restrict__ out, int start, int total)
{
    int i = start + blockIdx.x * blockDim.x + threadIdx.x;
    if (i < total) out[i] = 10.0f;
}

extern "C" void kernel_launch(void* const* d_in, const int* in_sizes, int n_in,
                              void* d_out, int out_size)
{
    const float* features = (const float*)d_in[0];
    const void*  ei       = d_in[1];
    const float* ew       = (const float*)d_in[2];
    const float* W1       = (const float*)d_in[3];
    const float* b1       = (const float*)d_in[4];
    const float* W2       = (const float*)d_in[5];
    const float* b2       = (const float*)d_in[6];
    float*       out      = (float*)d_out;

    const int N = in_sizes[0] / IN_DIM;
    const int E = in_sizes[2];

    float *X1, *P1, *X2, *H, *A, *B;
    cudaGetSymbolAddress((void**)&X1, gX1);
    cudaGetSymbolAddress((void**)&P1, gP1);
    cudaGetSymbolAddress((void**)&X2, gX2);
    cudaGetSymbolAddress((void**)&H,  gH);
    cudaGetSymbolAddress((void**)&A,  gA);
    cudaGetSymbolAddress((void**)&B,  gB);
    int* countPtr;
    cudaGetSymbolAddress((void**)&countPtr, gCount);

    // ---- CSR build (also runs concurrently-ish with GEMM1 in stream order) ----
    detect_idx_dtype<<<1, 1>>>(ei, N);
    cudaMemsetAsync(countPtr, 0, (size_t)N * sizeof(int));
    hist_dst<<<(E + 255) / 256, 256>>>(ei, E);
    scan_rowptr<<<1, 1024>>>(N, E);
    fill_csr<<<(E + 255) / 256, 256>>>(ei, ew, E);

    // ---- layer 1: X1 = features @ W1 ----
    {
        dim3 grid((N + 127) / 128, H_DIM / 128);
        sgemm_bias<128, 128, 16, 8, 8><<<grid, 256>>>(N, H_DIM, IN_DIM, features, W1, X1, nullptr);
    }
    // P1 = prop(X1)   (dim 128 gather)
    {
        int threads = 256, warpsPerBlk = threads / 32;
        gather_prop<H_DIM><<<(N + warpsPerBlk - 1) / warpsPerBlk, threads>>>(
            X1, P1, nullptr, nullptr, N, 1.0f, 0.0f);
    }
    // ---- layer 2: X2 = (P1 + b1) @ W2 ----
    {
        dim3 grid((N + 127) / 128, OUT_DIM / 64);
        sgemm_bias<128, 64, 16, 8, 4><<<grid, 256>>>(N, OUT_DIM, H_DIM, P1, W2, X2, b1);
    }
    // H = prop(X2) + b2   (dim 64 gather, bias fused)
    {
        int threads = 256, warpsPerBlk = threads / 32;
        gather_prop<OUT_DIM><<<(N + warpsPerBlk - 1) / warpsPerBlk, threads>>>(
            X2, H, nullptr, b2, N, 1.0f, 0.0f);
    }

    // ---- APPNP: x_{k+1} = (1-a)*prop(x_k) + a*h  (single fused gather per step) ----
    const float* xcur = H;
    for (int k = 0; k < K_STEPS; k++) {
        float* xnext = (k == K_STEPS - 1) ? out : ((k & 1) ? B : A);
        int threads = 256, warpsPerBlk = threads / 32;
        gather_prop<OUT_DIM><<<(N + warpsPerBlk - 1) / warpsPerBlk, threads>>>(
            xcur, xnext, H, nullptr, N, 1.0f - ALPHA_F, ALPHA_F);
        xcur = xnext;
    }

    // tail (reference returns (x, 10); fill any extra outputs with 10)
    int tail = out_size - N * OUT_DIM;
    if (tail > 0)
        fill_tail<<<(tail + 255) / 256, 256>>>(out, N * OUT_DIM, out_size);
}